// round 1
// baseline (speedup 1.0000x reference)
#include <cuda_runtime.h>
#include <math.h>

#define NN 100000
#define EE 1600000
#define HH 64
#define KK 32
#define INCH 161   // F + (F+2)K + H*F = 1 + 96 + 64

// ---------------- scratch (device globals; no runtime allocation) -------------
__device__ __align__(16) float g_xin [NN * HH];   // [N,64] input projection
__device__ __align__(16) float g_outf[NN * HH];   // [N,64] forward diffusion
__device__ __align__(16) float g_outb[NN * HH];   // [N,64] backward diffusion
__device__ __align__(16) float g_degf[NN];
__device__ __align__(16) float g_degb[NN];

// ---------------- packed f32x2 helpers (2x fp32 FMA throughput) ---------------
static __device__ __forceinline__ unsigned long long pack2(float lo, float hi) {
    unsigned long long r;
    asm("mov.b64 %0, {%1, %2};" : "=l"(r) : "f"(lo), "f"(hi));
    return r;
}
static __device__ __forceinline__ void unpack2(unsigned long long v, float& lo, float& hi) {
    asm("mov.b64 {%0, %1}, %2;" : "=f"(lo), "=f"(hi) : "l"(v));
}
static __device__ __forceinline__ void fma2(unsigned long long& d,
                                            unsigned long long a,
                                            unsigned long long b) {
    asm("fma.rn.f32x2 %0, %1, %2, %0;" : "+l"(d) : "l"(a), "l"(b));
}

// acc[0..2*NP-1] (f32x2 pairs) += (a,a) * Wrow[0..4*NP-1]
template <int NP>
static __device__ __forceinline__ void row_fma(unsigned long long* acc,
                                               const float* Wrow,
                                               unsigned long long a2) {
    const ulonglong2* w = reinterpret_cast<const ulonglong2*>(Wrow);
#pragma unroll
    for (int j = 0; j < NP; j++) {
        ulonglong2 wv = w[j];
        fma2(acc[2 * j + 0], a2, wv.x);
        fma2(acc[2 * j + 1], a2, wv.y);
    }
}

// ---------------- k0: zero scratch --------------------------------------------
__global__ void k_zero() {
    int i = blockIdx.x * blockDim.x + threadIdx.x;
    float4 z = make_float4(0.f, 0.f, 0.f, 0.f);
    if (i < NN * HH / 4) {
        reinterpret_cast<float4*>(g_outf)[i] = z;
        reinterpret_cast<float4*>(g_outb)[i] = z;
    }
    if (i < NN / 4) {
        reinterpret_cast<float4*>(g_degf)[i] = z;
        reinterpret_cast<float4*>(g_degb)[i] = z;
    }
}

// ---------------- k1: weighted degrees ----------------------------------------
__global__ void k_deg(const int* __restrict__ ei, const float* __restrict__ ew) {
    int e = blockIdx.x * blockDim.x + threadIdx.x;
    if (e >= EE) return;
    int   s = ei[e];
    int   t = ei[EE + e];
    float w = ew[e];
    if (s == t || w == 0.f) return;
    atomicAdd(&g_degf[t], w);
    atomicAdd(&g_degb[s], w);
}

// ---------------- k2: input projection x_in = [x|xhat|h] @ W_in + b_in --------
__global__ __launch_bounds__(128) void k_proj(const float* __restrict__ x,
                                              const float* __restrict__ xh,
                                              const float* __restrict__ h,
                                              const float* __restrict__ Win,
                                              const float* __restrict__ bin) {
    __shared__ __align__(16) float Ws[INCH * HH];   // 41216 B
    for (int i = threadIdx.x; i < INCH * HH; i += 128) Ws[i] = Win[i];
    __syncthreads();

    int n = blockIdx.x * 128 + threadIdx.x;
    if (n >= NN) return;

    unsigned long long acc[32];
#pragma unroll
    for (int j = 0; j < 32; j++) acc[j] = pack2(bin[2 * j], bin[2 * j + 1]);

    // k = 0 : x
    {
        float a = x[n];
        row_fma<16>(acc, Ws, pack2(a, a));
    }
    // k = 1..96 : x_hat_1 (96 values)
    const float4* xh4 = reinterpret_cast<const float4*>(xh + (size_t)n * 96);
#pragma unroll 4
    for (int kk = 0; kk < 24; kk++) {
        float4 av = xh4[kk];
        float  avv[4] = {av.x, av.y, av.z, av.w};
#pragma unroll
        for (int u = 0; u < 4; u++) {
            int k = 1 + kk * 4 + u;
            row_fma<16>(acc, Ws + k * HH, pack2(avv[u], avv[u]));
        }
    }
    // k = 97..160 : h (64 values)
    const float4* h4 = reinterpret_cast<const float4*>(h + (size_t)n * 64);
#pragma unroll 4
    for (int kk = 0; kk < 16; kk++) {
        float4 av = h4[kk];
        float  avv[4] = {av.x, av.y, av.z, av.w};
#pragma unroll
        for (int u = 0; u < 4; u++) {
            int k = 97 + kk * 4 + u;
            row_fma<16>(acc, Ws + k * HH, pack2(avv[u], avv[u]));
        }
    }

    float2* o = reinterpret_cast<float2*>(g_xin + (size_t)n * HH);
#pragma unroll
    for (int j = 0; j < 32; j++) {
        float lo, hi;
        unpack2(acc[j], lo, hi);
        o[j] = make_float2(lo, hi);
    }
}

// ---------------- k3: edge diffusion scatter (16 threads / edge) --------------
__global__ void k_diff(const int* __restrict__ ei, const float* __restrict__ ew) {
    int idx = blockIdx.x * blockDim.x + threadIdx.x;
    int e = idx >> 4;
    int c = idx & 15;
    if (e >= EE) return;
    int   s = ei[e];
    int   t = ei[EE + e];
    float w = ew[e];
    if (s == t || w == 0.f) return;
    float df = g_degf[t];
    float db = g_degb[s];
    float wf = w / (df > 0.f ? df : 1.f);
    float wb = w / (db > 0.f ? db : 1.f);

    const float4* xin4 = reinterpret_cast<const float4*>(g_xin);
    float4 a = xin4[(size_t)s * 16 + c];
    float* of = g_outf + (size_t)t * 64 + c * 4;
    atomicAdd(of + 0, wf * a.x);
    atomicAdd(of + 1, wf * a.y);
    atomicAdd(of + 2, wf * a.z);
    atomicAdd(of + 3, wf * a.w);

    float4 b = xin4[(size_t)t * 16 + c];
    float* ob = g_outb + (size_t)s * 64 + c * 4;
    atomicAdd(ob + 0, wb * b.x);
    atomicAdd(ob + 1, wb * b.y);
    atomicAdd(ob + 2, wb * b.z);
    atomicAdd(ob + 3, wb * b.w);
}

// ---------------- k4: out = [of|ob]@W_filt + b; write out1=[out|h] and h tail --
__global__ __launch_bounds__(128) void k_filt(const float* __restrict__ h,
                                              const float* __restrict__ Wf,
                                              const float* __restrict__ bf,
                                              float* __restrict__ out1,
                                              float* __restrict__ hout) {
    __shared__ __align__(16) float Ws[128 * HH];    // 32 KB
    for (int i = threadIdx.x; i < 128 * HH; i += 128) Ws[i] = Wf[i];
    __syncthreads();

    int n = blockIdx.x * 128 + threadIdx.x;
    if (n >= NN) return;

    unsigned long long acc[32];
#pragma unroll
    for (int j = 0; j < 32; j++) acc[j] = pack2(bf[2 * j], bf[2 * j + 1]);

    const float4* a4 = reinterpret_cast<const float4*>(g_outf + (size_t)n * 64);
#pragma unroll 4
    for (int kk = 0; kk < 16; kk++) {
        float4 av = a4[kk];
        float  avv[4] = {av.x, av.y, av.z, av.w};
#pragma unroll
        for (int u = 0; u < 4; u++)
            row_fma<16>(acc, Ws + (kk * 4 + u) * HH, pack2(avv[u], avv[u]));
    }
    const float4* b4 = reinterpret_cast<const float4*>(g_outb + (size_t)n * 64);
#pragma unroll 4
    for (int kk = 0; kk < 16; kk++) {
        float4 av = b4[kk];
        float  avv[4] = {av.x, av.y, av.z, av.w};
#pragma unroll
        for (int u = 0; u < 4; u++)
            row_fma<16>(acc, Ws + (64 + kk * 4 + u) * HH, pack2(avv[u], avv[u]));
    }

    // out1[n] = [out(64) | h(64)]
    float2* o = reinterpret_cast<float2*>(out1 + (size_t)n * 128);
#pragma unroll
    for (int j = 0; j < 32; j++) {
        float lo, hi;
        unpack2(acc[j], lo, hi);
        o[j] = make_float2(lo, hi);
    }
    const float4* h4 = reinterpret_cast<const float4*>(h + (size_t)n * 64);
    float4* o2 = reinterpret_cast<float4*>(out1 + (size_t)n * 128 + 64);
    float4* ho = reinterpret_cast<float4*>(hout + (size_t)n * 64);
#pragma unroll
    for (int j = 0; j < 16; j++) {
        float4 v = h4[j];
        o2[j] = v;
        ho[j] = v;   // third output: h passthrough
    }
}

// ---------------- k5: mu head --------------------------------------------------
__global__ __launch_bounds__(128) void k_mu(const float* __restrict__ out1,
                                            const float* __restrict__ Wm,
                                            const float* __restrict__ bm,
                                            float* __restrict__ gmm) {
    __shared__ __align__(16) float Ws[128 * KK];    // 16 KB
    for (int i = threadIdx.x; i < 128 * KK; i += 128) Ws[i] = Wm[i];
    __syncthreads();

    int n = blockIdx.x * 128 + threadIdx.x;
    if (n >= NN) return;

    unsigned long long acc[16];
#pragma unroll
    for (int j = 0; j < 16; j++) acc[j] = pack2(bm[2 * j], bm[2 * j + 1]);

    const float4* a4 = reinterpret_cast<const float4*>(out1 + (size_t)n * 128);
#pragma unroll 4
    for (int kk = 0; kk < 32; kk++) {
        float4 av = a4[kk];
        float  avv[4] = {av.x, av.y, av.z, av.w};
#pragma unroll
        for (int u = 0; u < 4; u++)
            row_fma<8>(acc, Ws + (kk * 4 + u) * KK, pack2(avv[u], avv[u]));
    }

    float2* o = reinterpret_cast<float2*>(gmm + (size_t)n * 96);
#pragma unroll
    for (int j = 0; j < 16; j++) {
        float lo, hi;
        unpack2(acc[j], lo, hi);
        o[j] = make_float2(lo, hi);
    }
}

// ---------------- k6: sigma (softplus) + pi (softmax) heads -------------------
__global__ __launch_bounds__(128) void k_sigpi(const float* __restrict__ out1,
                                               const float* __restrict__ Wsg,
                                               const float* __restrict__ bsg,
                                               const float* __restrict__ Wp,
                                               const float* __restrict__ bp,
                                               float* __restrict__ gmm) {
    __shared__ __align__(16) float Ws[128 * KK];    // 16 KB
    __shared__ __align__(16) float Wq[128 * KK];    // 16 KB
    for (int i = threadIdx.x; i < 128 * KK; i += 128) {
        Ws[i] = Wsg[i];
        Wq[i] = Wp[i];
    }
    __syncthreads();

    int n = blockIdx.x * 128 + threadIdx.x;
    if (n >= NN) return;

    unsigned long long accS[16], accP[16];
#pragma unroll
    for (int j = 0; j < 16; j++) {
        accS[j] = pack2(bsg[2 * j], bsg[2 * j + 1]);
        accP[j] = pack2(bp[2 * j], bp[2 * j + 1]);
    }

    const float4* a4 = reinterpret_cast<const float4*>(out1 + (size_t)n * 128);
#pragma unroll 2
    for (int kk = 0; kk < 32; kk++) {
        float4 av = a4[kk];
        float  avv[4] = {av.x, av.y, av.z, av.w};
#pragma unroll
        for (int u = 0; u < 4; u++) {
            int k = kk * 4 + u;
            unsigned long long a2 = pack2(avv[u], avv[u]);
            row_fma<8>(accS, Ws + k * KK, a2);
            row_fma<8>(accP, Wq + k * KK, a2);
        }
    }

    float sv[32], pv[32];
#pragma unroll
    for (int j = 0; j < 16; j++) {
        unpack2(accS[j], sv[2 * j], sv[2 * j + 1]);
        unpack2(accP[j], pv[2 * j], pv[2 * j + 1]);
    }

    // softplus(sigma): stable log1p(exp(x))
#pragma unroll
    for (int j = 0; j < 32; j++)
        sv[j] = (sv[j] > 20.f) ? sv[j] : log1pf(expf(sv[j]));

    // softmax(pi) over K=32 (in-thread)
    float m = pv[0];
#pragma unroll
    for (int j = 1; j < 32; j++) m = fmaxf(m, pv[j]);
    float sum = 0.f;
#pragma unroll
    for (int j = 0; j < 32; j++) {
        pv[j] = expf(pv[j] - m);
        sum += pv[j];
    }
    float inv = 1.f / sum;
#pragma unroll
    for (int j = 0; j < 32; j++) pv[j] *= inv;

    float* o = gmm + (size_t)n * 96;
    float4* os = reinterpret_cast<float4*>(o + 32);
    float4* op = reinterpret_cast<float4*>(o + 64);
#pragma unroll
    for (int j = 0; j < 8; j++) {
        os[j] = make_float4(sv[4 * j], sv[4 * j + 1], sv[4 * j + 2], sv[4 * j + 3]);
        op[j] = make_float4(pv[4 * j], pv[4 * j + 1], pv[4 * j + 2], pv[4 * j + 3]);
    }
}

// ---------------- launch -------------------------------------------------------
extern "C" void kernel_launch(void* const* d_in, const int* in_sizes, int n_in,
                              void* d_out, int out_size) {
    const float* x   = (const float*)d_in[0];
    const float* xh  = (const float*)d_in[1];
    const float* h   = (const float*)d_in[2];
    const int*   ei  = (const int*)d_in[3];
    const float* ew  = (const float*)d_in[4];
    const float* Win = (const float*)d_in[5];
    const float* bin = (const float*)d_in[6];
    const float* Wf  = (const float*)d_in[7];
    const float* bf  = (const float*)d_in[8];
    const float* Wm  = (const float*)d_in[9];
    const float* bm  = (const float*)d_in[10];
    const float* Wsg = (const float*)d_in[11];
    const float* bsg = (const float*)d_in[12];
    const float* Wp  = (const float*)d_in[13];
    const float* bp  = (const float*)d_in[14];

    float* out  = (float*)d_out;
    float* gmm  = out;                          // [N, 96]
    float* out1 = out + (size_t)NN * 96;        // [N, 128]
    float* hout = out1 + (size_t)NN * 128;      // [N, 64]

    k_zero<<<(NN * HH / 4 + 255) / 256, 256>>>();
    k_deg<<<(EE + 255) / 256, 256>>>(ei, ew);
    k_proj<<<(NN + 127) / 128, 128>>>(x, xh, h, Win, bin);
    k_diff<<<(EE * 16) / 256, 256>>>(ei, ew);
    k_filt<<<(NN + 127) / 128, 128>>>(h, Wf, bf, out1, hout);
    k_mu<<<(NN + 127) / 128, 128>>>(out1, Wm, bm, gmm);
    k_sigpi<<<(NN + 127) / 128, 128>>>(out1, Wsg, bsg, Wp, bp, gmm);
}

// round 2
// speedup vs baseline: 1.5742x; 1.5742x over previous
#include <cuda_runtime.h>
#include <math.h>

#define NN 100000
#define EE 1600000
#define HH 64
#define KK 32
#define INCH 161   // F + (F+2)K + H*F = 1 + 96 + 64

// ---------------- scratch (device globals; no runtime allocation) -------------
__device__ __align__(16) float g_xin [NN * HH];   // [N,64] input projection
__device__ __align__(16) float g_outf[NN * HH];   // [N,64] forward diffusion
__device__ __align__(16) float g_outb[NN * HH];   // [N,64] backward diffusion
__device__ __align__(16) float g_degf[NN];        // becomes reciprocal after k_rdeg
__device__ __align__(16) float g_degb[NN];

// ---------------- packed f32x2 helpers (2x fp32 FMA throughput) ---------------
static __device__ __forceinline__ unsigned long long pack2(float lo, float hi) {
    unsigned long long r;
    asm("mov.b64 %0, {%1, %2};" : "=l"(r) : "f"(lo), "f"(hi));
    return r;
}
static __device__ __forceinline__ void unpack2(unsigned long long v, float& lo, float& hi) {
    asm("mov.b64 {%0, %1}, %2;" : "=f"(lo), "=f"(hi) : "l"(v));
}
static __device__ __forceinline__ void fma2(unsigned long long& d,
                                            unsigned long long a,
                                            unsigned long long b) {
    asm("fma.rn.f32x2 %0, %1, %2, %0;" : "+l"(d) : "l"(a), "l"(b));
}

// acc[0..2*NP-1] (f32x2 pairs) += (a,a) * Wrow[0..4*NP-1]
template <int NP>
static __device__ __forceinline__ void row_fma(unsigned long long* acc,
                                               const float* Wrow,
                                               unsigned long long a2) {
    const ulonglong2* w = reinterpret_cast<const ulonglong2*>(Wrow);
#pragma unroll
    for (int j = 0; j < NP; j++) {
        ulonglong2 wv = w[j];
        fma2(acc[2 * j + 0], a2, wv.x);
        fma2(acc[2 * j + 1], a2, wv.y);
    }
}

// vectorized no-return global reduction (sm_90+)
static __device__ __forceinline__ void red_add_v4(float* ptr, float a, float b,
                                                  float c, float d) {
    asm volatile("red.global.add.v4.f32 [%0], {%1, %2, %3, %4};"
                 :: "l"(ptr), "f"(a), "f"(b), "f"(c), "f"(d) : "memory");
}

// ---------------- k0: zero scratch --------------------------------------------
__global__ void k_zero() {
    int i = blockIdx.x * blockDim.x + threadIdx.x;
    float4 z = make_float4(0.f, 0.f, 0.f, 0.f);
    if (i < NN * HH / 4) {
        reinterpret_cast<float4*>(g_outf)[i] = z;
        reinterpret_cast<float4*>(g_outb)[i] = z;
    }
    if (i < NN / 4) {
        reinterpret_cast<float4*>(g_degf)[i] = z;
        reinterpret_cast<float4*>(g_degb)[i] = z;
    }
}

// ---------------- k1: weighted degrees ----------------------------------------
__global__ void k_deg(const int* __restrict__ ei, const float* __restrict__ ew) {
    int e = blockIdx.x * blockDim.x + threadIdx.x;
    if (e >= EE) return;
    int   s = ei[e];
    int   t = ei[EE + e];
    float w = ew[e];
    if (s == t || w == 0.f) return;
    atomicAdd(&g_degf[t], w);
    atomicAdd(&g_degb[s], w);
}

// ---------------- k1b: reciprocal degrees (once per node, not per edge) -------
__global__ void k_rdeg() {
    int n = blockIdx.x * blockDim.x + threadIdx.x;
    if (n >= NN) return;
    float df = g_degf[n];
    float db = g_degb[n];
    g_degf[n] = (df > 0.f) ? (1.0f / df) : 1.0f;
    g_degb[n] = (db > 0.f) ? (1.0f / db) : 1.0f;
}

// ---------------- k2: input projection x_in = [x|xhat|h] @ W_in + b_in --------
__global__ __launch_bounds__(128) void k_proj(const float* __restrict__ x,
                                              const float* __restrict__ xh,
                                              const float* __restrict__ h,
                                              const float* __restrict__ Win,
                                              const float* __restrict__ bin) {
    __shared__ __align__(16) float Ws[INCH * HH];   // 41216 B
    for (int i = threadIdx.x; i < INCH * HH; i += 128) Ws[i] = Win[i];
    __syncthreads();

    int n = blockIdx.x * 128 + threadIdx.x;
    if (n >= NN) return;

    unsigned long long acc[32];
#pragma unroll
    for (int j = 0; j < 32; j++) acc[j] = pack2(bin[2 * j], bin[2 * j + 1]);

    // k = 0 : x
    {
        float a = x[n];
        row_fma<16>(acc, Ws, pack2(a, a));
    }
    // k = 1..96 : x_hat_1 (96 values)
    const float4* xh4 = reinterpret_cast<const float4*>(xh + (size_t)n * 96);
#pragma unroll 4
    for (int kk = 0; kk < 24; kk++) {
        float4 av = xh4[kk];
        float  avv[4] = {av.x, av.y, av.z, av.w};
#pragma unroll
        for (int u = 0; u < 4; u++) {
            int k = 1 + kk * 4 + u;
            row_fma<16>(acc, Ws + k * HH, pack2(avv[u], avv[u]));
        }
    }
    // k = 97..160 : h (64 values)
    const float4* h4 = reinterpret_cast<const float4*>(h + (size_t)n * 64);
#pragma unroll 4
    for (int kk = 0; kk < 16; kk++) {
        float4 av = h4[kk];
        float  avv[4] = {av.x, av.y, av.z, av.w};
#pragma unroll
        for (int u = 0; u < 4; u++) {
            int k = 97 + kk * 4 + u;
            row_fma<16>(acc, Ws + k * HH, pack2(avv[u], avv[u]));
        }
    }

    float2* o = reinterpret_cast<float2*>(g_xin + (size_t)n * HH);
#pragma unroll
    for (int j = 0; j < 32; j++) {
        float lo, hi;
        unpack2(acc[j], lo, hi);
        o[j] = make_float2(lo, hi);
    }
}

// ---------------- k3: edge diffusion scatter (16 threads / edge) --------------
// Per-thread: 2 float4 gathers + 2 red.global.add.v4 (coalesced 256B per edge).
__global__ void k_diff(const int* __restrict__ ei, const float* __restrict__ ew) {
    int idx = blockIdx.x * blockDim.x + threadIdx.x;
    int e = idx >> 4;
    int c = idx & 15;
    if (e >= EE) return;
    int   s = ei[e];
    int   t = ei[EE + e];
    float w = ew[e];
    if (s == t || w == 0.f) return;
    float wf = w * g_degf[t];   // reciprocal degrees precomputed
    float wb = w * g_degb[s];

    const float4* xin4 = reinterpret_cast<const float4*>(g_xin);
    float4 a = xin4[(size_t)s * 16 + c];
    red_add_v4(g_outf + (size_t)t * 64 + c * 4,
               wf * a.x, wf * a.y, wf * a.z, wf * a.w);

    float4 b = xin4[(size_t)t * 16 + c];
    red_add_v4(g_outb + (size_t)s * 64 + c * 4,
               wb * b.x, wb * b.y, wb * b.z, wb * b.w);
}

// ---------------- k4: out = [of|ob]@W_filt + b; write out1=[out|h] and h tail --
__global__ __launch_bounds__(128) void k_filt(const float* __restrict__ h,
                                              const float* __restrict__ Wf,
                                              const float* __restrict__ bf,
                                              float* __restrict__ out1,
                                              float* __restrict__ hout) {
    __shared__ __align__(16) float Ws[128 * HH];    // 32 KB
    for (int i = threadIdx.x; i < 128 * HH; i += 128) Ws[i] = Wf[i];
    __syncthreads();

    int n = blockIdx.x * 128 + threadIdx.x;
    if (n >= NN) return;

    unsigned long long acc[32];
#pragma unroll
    for (int j = 0; j < 32; j++) acc[j] = pack2(bf[2 * j], bf[2 * j + 1]);

    const float4* a4 = reinterpret_cast<const float4*>(g_outf + (size_t)n * 64);
#pragma unroll 4
    for (int kk = 0; kk < 16; kk++) {
        float4 av = a4[kk];
        float  avv[4] = {av.x, av.y, av.z, av.w};
#pragma unroll
        for (int u = 0; u < 4; u++)
            row_fma<16>(acc, Ws + (kk * 4 + u) * HH, pack2(avv[u], avv[u]));
    }
    const float4* b4 = reinterpret_cast<const float4*>(g_outb + (size_t)n * 64);
#pragma unroll 4
    for (int kk = 0; kk < 16; kk++) {
        float4 av = b4[kk];
        float  avv[4] = {av.x, av.y, av.z, av.w};
#pragma unroll
        for (int u = 0; u < 4; u++)
            row_fma<16>(acc, Ws + (64 + kk * 4 + u) * HH, pack2(avv[u], avv[u]));
    }

    // out1[n] = [out(64) | h(64)]
    float2* o = reinterpret_cast<float2*>(out1 + (size_t)n * 128);
#pragma unroll
    for (int j = 0; j < 32; j++) {
        float lo, hi;
        unpack2(acc[j], lo, hi);
        o[j] = make_float2(lo, hi);
    }
    const float4* h4 = reinterpret_cast<const float4*>(h + (size_t)n * 64);
    float4* o2 = reinterpret_cast<float4*>(out1 + (size_t)n * 128 + 64);
    float4* ho = reinterpret_cast<float4*>(hout + (size_t)n * 64);
#pragma unroll
    for (int j = 0; j < 16; j++) {
        float4 v = h4[j];
        o2[j] = v;
        ho[j] = v;   // third output: h passthrough
    }
}

// ---------------- k5: fused GMM heads (mu | softplus sigma | softmax pi) ------
__global__ __launch_bounds__(128) void k_heads(const float* __restrict__ out1,
                                               const float* __restrict__ Wm,
                                               const float* __restrict__ bm,
                                               const float* __restrict__ Wsg,
                                               const float* __restrict__ bsg,
                                               const float* __restrict__ Wp,
                                               const float* __restrict__ bp,
                                               float* __restrict__ gmm) {
    __shared__ __align__(16) float Wms[128 * KK];   // 16 KB
    __shared__ __align__(16) float Wss[128 * KK];   // 16 KB
    __shared__ __align__(16) float Wps[128 * KK];   // 16 KB
    for (int i = threadIdx.x; i < 128 * KK; i += 128) {
        Wms[i] = Wm[i];
        Wss[i] = Wsg[i];
        Wps[i] = Wp[i];
    }
    __syncthreads();

    int n = blockIdx.x * 128 + threadIdx.x;
    if (n >= NN) return;

    unsigned long long accM[16], accS[16], accP[16];
#pragma unroll
    for (int j = 0; j < 16; j++) {
        accM[j] = pack2(bm[2 * j], bm[2 * j + 1]);
        accS[j] = pack2(bsg[2 * j], bsg[2 * j + 1]);
        accP[j] = pack2(bp[2 * j], bp[2 * j + 1]);
    }

    const float4* a4 = reinterpret_cast<const float4*>(out1 + (size_t)n * 128);
#pragma unroll 2
    for (int kk = 0; kk < 32; kk++) {
        float4 av = a4[kk];
        float  avv[4] = {av.x, av.y, av.z, av.w};
#pragma unroll
        for (int u = 0; u < 4; u++) {
            int k = kk * 4 + u;
            unsigned long long a2 = pack2(avv[u], avv[u]);
            row_fma<8>(accM, Wms + k * KK, a2);
            row_fma<8>(accS, Wss + k * KK, a2);
            row_fma<8>(accP, Wps + k * KK, a2);
        }
    }

    float* o = gmm + (size_t)n * 96;

    // mu (direct write)
    float2* om = reinterpret_cast<float2*>(o);
#pragma unroll
    for (int j = 0; j < 16; j++) {
        float lo, hi;
        unpack2(accM[j], lo, hi);
        om[j] = make_float2(lo, hi);
    }

    float sv[32], pv[32];
#pragma unroll
    for (int j = 0; j < 16; j++) {
        unpack2(accS[j], sv[2 * j], sv[2 * j + 1]);
        unpack2(accP[j], pv[2 * j], pv[2 * j + 1]);
    }

    // softplus(sigma): stable log1p(exp(x))
#pragma unroll
    for (int j = 0; j < 32; j++)
        sv[j] = (sv[j] > 20.f) ? sv[j] : log1pf(expf(sv[j]));

    // softmax(pi) over K=32 (in-thread)
    float m = pv[0];
#pragma unroll
    for (int j = 1; j < 32; j++) m = fmaxf(m, pv[j]);
    float sum = 0.f;
#pragma unroll
    for (int j = 0; j < 32; j++) {
        pv[j] = expf(pv[j] - m);
        sum += pv[j];
    }
    float inv = 1.f / sum;
#pragma unroll
    for (int j = 0; j < 32; j++) pv[j] *= inv;

    float4* os = reinterpret_cast<float4*>(o + 32);
    float4* op = reinterpret_cast<float4*>(o + 64);
#pragma unroll
    for (int j = 0; j < 8; j++) {
        os[j] = make_float4(sv[4 * j], sv[4 * j + 1], sv[4 * j + 2], sv[4 * j + 3]);
        op[j] = make_float4(pv[4 * j], pv[4 * j + 1], pv[4 * j + 2], pv[4 * j + 3]);
    }
}

// ---------------- launch -------------------------------------------------------
extern "C" void kernel_launch(void* const* d_in, const int* in_sizes, int n_in,
                              void* d_out, int out_size) {
    const float* x   = (const float*)d_in[0];
    const float* xh  = (const float*)d_in[1];
    const float* h   = (const float*)d_in[2];
    const int*   ei  = (const int*)d_in[3];
    const float* ew  = (const float*)d_in[4];
    const float* Win = (const float*)d_in[5];
    const float* bin = (const float*)d_in[6];
    const float* Wf  = (const float*)d_in[7];
    const float* bf  = (const float*)d_in[8];
    const float* Wm  = (const float*)d_in[9];
    const float* bm  = (const float*)d_in[10];
    const float* Wsg = (const float*)d_in[11];
    const float* bsg = (const float*)d_in[12];
    const float* Wp  = (const float*)d_in[13];
    const float* bp  = (const float*)d_in[14];

    float* out  = (float*)d_out;
    float* gmm  = out;                          // [N, 96]
    float* out1 = out + (size_t)NN * 96;        // [N, 128]
    float* hout = out1 + (size_t)NN * 128;      // [N, 64]

    k_zero<<<(NN * HH / 4 + 255) / 256, 256>>>();
    k_deg<<<(EE + 255) / 256, 256>>>(ei, ew);
    k_rdeg<<<(NN + 255) / 256, 256>>>();
    k_proj<<<(NN + 127) / 128, 128>>>(x, xh, h, Win, bin);
    k_diff<<<(EE * 16) / 256, 256>>>(ei, ew);
    k_filt<<<(NN + 127) / 128, 128>>>(h, Wf, bf, out1, hout);
    k_heads<<<(NN + 127) / 128, 128>>>(out1, Wm, bm, Wsg, bsg, Wp, bp, gmm);
}